// round 13
// baseline (speedup 1.0000x reference)
#include <cuda_runtime.h>

// _QuantumLSTMCell: analytic collapse of the 4-qubit circuit.
// angles = comb @ W^T + b ; z_w = cos(angle_w + th_w)
// E0 = z1 z2 z3 ; E1 = z0 z1 ; E2 = z0 z1 z2 ; E3 = z0 z1 z2 z3
// f,i,o = sigmoid(E), g = tanh(E_u); c' = f*cx + i*g; h' = o*tanh(c')
// out = [h_new (B*4) | c_new (B*4)]
//
// R13: ALL weights in __constant__ (separate const port, warp-uniform LDC),
// zero weight-LDS -- L1 carries only x traffic. RPT=1, 16 j per thread,
// thread-owns-row epilogue (no exchange). Warp-private cp.async pipeline.

#define THREADS 128
#define WARPS 4
#define ROWS_WARP 32                 // lane <-> row
#define ROWS_BLK (WARPS * ROWS_WARP) // 128
#define D_COLS 256
#define NJ 16
#define TILE_K 16
#define NTILES (D_COLS / TILE_K)     // 16
#define PITCH 20                     // floats per staged row (conflict-free)
#define STAGE_F (ROWS_WARP * PITCH)  // 640 floats per warp-stage

typedef unsigned long long u64;

// raw weight image: cW[j*260 + k], j = gate*4 + wire (f,i,u,o)
__constant__ float cW[4 * 1040];

__device__ __forceinline__ u64 pk(float lo, float hi) {
    u64 r; asm("mov.b64 %0, {%1,%2};" : "=l"(r) : "f"(lo), "f"(hi)); return r;
}
__device__ __forceinline__ void upk(u64 v, float& lo, float& hi) {
    asm("mov.b64 {%0,%1}, %2;" : "=f"(lo), "=f"(hi) : "l"(v));
}
__device__ __forceinline__ void fma2(u64& d, u64 a, u64 b) {
    asm("fma.rn.f32x2 %0, %1, %2, %0;" : "+l"(d) : "l"(a), "l"(b));
}
__device__ __forceinline__ void cp16(unsigned dst, const void* src) {
    asm volatile("cp.async.cg.shared.global [%0], [%1], 16;" :: "r"(dst), "l"(src));
}
__device__ __forceinline__ void cp_commit() {
    asm volatile("cp.async.commit_group;");
}
__device__ __forceinline__ void cp_wait1() {
    asm volatile("cp.async.wait_group 1;");
}
__device__ __forceinline__ void cp_wait0() {
    asm volatile("cp.async.wait_group 0;");
}

__device__ __forceinline__ float sigmoidf_(float x) {
    return 1.0f / (1.0f + __expf(-x));
}
__device__ __forceinline__ float tanhf_(float x) {
    return 1.0f - 2.0f / (__expf(2.0f * x) + 1.0f);
}

// issue one TILE_K=16 tile (32 rows x 64 B) for this warp: 4 cp16/lane,
// each warp-instr = 8 rows x 64 B contiguous; STS side conflict-free.
__device__ __forceinline__ void issue_tile(unsigned xs_s, const float* xw,
                                           int lane, int tile, int slot) {
#pragma unroll
    for (int i = 0; i < 4; i++) {
        int rl = i * 8 + (lane >> 2);
        int ch = lane & 3;
        cp16(xs_s + (unsigned)((slot * STAGE_F + rl * PITCH + ch * 4) * 4),
             xw + (size_t)rl * D_COLS + tile * TILE_K + ch * 4);
    }
    cp_commit();
}

// one kq group (4 k, starting at uniform k0): x pairs vs all 16 j from const
__device__ __forceinline__ void do_kq(u64 acc[NJ], ulonglong2 xv, int k0) {
#pragma unroll
    for (int j = 0; j < NJ; j++) {
        ulonglong2 w = *(const ulonglong2*)&cW[j * 260 + k0];  // uniform LDC.128
        fma2(acc[j], xv.x, w.x);
        fma2(acc[j], xv.y, w.y);
    }
}

__global__ void __launch_bounds__(THREADS, 6)
qlstm_kernel(const float* __restrict__ x, const float* __restrict__ hx,
             const float* __restrict__ cx,
             const float* __restrict__ bf, const float* __restrict__ bi,
             const float* __restrict__ bu, const float* __restrict__ bo,
             const float* __restrict__ tf, const float* __restrict__ ti,
             const float* __restrict__ tu, const float* __restrict__ to,
             float* __restrict__ out, int B)
{
    __shared__ __align__(16) float xs[WARPS * 2 * STAGE_F];   // 20,480 B
    __shared__ float sphase[NJ];

    const int tid  = threadIdx.x;
    const int wid  = tid >> 5;
    const int lane = tid & 31;

    const int warpRow0 = blockIdx.x * ROWS_BLK + wid * ROWS_WARP;
    const float* xw = x + (size_t)warpRow0 * D_COLS;

    float* xs_w = xs + wid * (2 * STAGE_F);
    unsigned xs_s = (unsigned)__cvta_generic_to_shared(xs_w);

    // ---- prologue: tiles 0,1 ----
    issue_tile(xs_s, xw, lane, 0, 0);
    issue_tile(xs_s, xw, lane, 1, 1);

    // ---- phases (only smem staging left) ----
    if (tid < NJ) {
        int j = tid, gate = j >> 2, wire = j & 3;
        const float* bb = (gate == 0) ? bf : (gate == 1) ? bi
                        : (gate == 2) ? bu : bo;
        const float* tt = (gate == 0) ? tf : (gate == 1) ? ti
                        : (gate == 2) ? tu : to;
        sphase[j] = bb[wire] + tt[wire];
    }
    __syncthreads();   // the ONLY block barrier

    u64 acc[NJ];
#pragma unroll
    for (int j = 0; j < NJ; j++) acc[j] = 0ull;

    // ---- warp-private pipelined main loop ----
#pragma unroll 1
    for (int t = 0; t < NTILES; t++) {
        if (t == NTILES - 1) cp_wait0(); else cp_wait1();
        __syncwarp();

        const float* xb = xs_w + (t & 1) * STAGE_F;
#pragma unroll
        for (int kq = 0; kq < 4; kq++) {
            ulonglong2 xv = *(const ulonglong2*)(xb + lane * PITCH + kq * 4);
            do_kq(acc, xv, t * TILE_K + kq * 4);
        }
        __syncwarp();

        if (t + 2 < NTILES)
            issue_tile(xs_s, xw, lane, t + 2, t & 1);
    }

    // ---- hx tail: k = 256..259 (coalesced: lane -> row) ----
    {
        ulonglong2 hv = ((const ulonglong2*)hx)[warpRow0 + lane];
        do_kq(acc, hv, 256);
    }

    // ---- epilogue: thread owns its full row ----
    const int row = warpRow0 + lane;
    float z[NJ];
#pragma unroll
    for (int j = 0; j < NJ; j++) {
        float lo, hi; upk(acc[j], lo, hi);
        z[j] = __cosf(lo + hi + sphase[j]);
    }
    float e[NJ];
#pragma unroll
    for (int g = 0; g < 4; g++) {
        float z0 = z[g*4+0], z1 = z[g*4+1], z2 = z[g*4+2], z3 = z[g*4+3];
        float p01 = z0 * z1;
        e[g*4+0] = z1 * z2 * z3;
        e[g*4+1] = p01;
        e[g*4+2] = p01 * z2;
        e[g*4+3] = p01 * z2 * z3;
    }
    float4 cxv = ((const float4*)cx)[row];
    float cxa[4] = {cxv.x, cxv.y, cxv.z, cxv.w};
    float hn[4], cn[4];
#pragma unroll
    for (int w = 0; w < 4; w++) {
        float fv = sigmoidf_(e[0*4+w]);
        float iv = sigmoidf_(e[1*4+w]);
        float gv = tanhf_(e[2*4+w]);
        float ov = sigmoidf_(e[3*4+w]);
        float c = fv * cxa[w] + iv * gv;
        cn[w] = c;
        hn[w] = ov * tanhf_(c);
    }
    ((float4*)out)[row] = make_float4(hn[0], hn[1], hn[2], hn[3]);
    ((float4*)(out + (size_t)B * 4))[row] = make_float4(cn[0], cn[1], cn[2], cn[3]);
}

extern "C" void kernel_launch(void* const* d_in, const int* in_sizes, int n_in,
                              void* d_out, int out_size) {
    const float* x  = (const float*)d_in[0];
    const float* hx = (const float*)d_in[1];
    const float* cx = (const float*)d_in[2];
    const float* Wf = (const float*)d_in[3];
    const float* bf = (const float*)d_in[4];
    const float* Wi = (const float*)d_in[5];
    const float* bi = (const float*)d_in[6];
    const float* Wu = (const float*)d_in[7];
    const float* bu = (const float*)d_in[8];
    const float* Wo = (const float*)d_in[9];
    const float* bo = (const float*)d_in[10];
    const float* tf = (const float*)d_in[11];
    const float* ti = (const float*)d_in[12];
    const float* tu = (const float*)d_in[13];
    const float* to = (const float*)d_in[14];
    float* out = (float*)d_out;

    int B = in_sizes[0] / D_COLS;                 // 131072
    int grid = (B + ROWS_BLK - 1) / ROWS_BLK;     // 1024

    // raw weight images straight into constant memory (D2D, graph-capturable)
    const size_t GB = 1040 * sizeof(float);
    cudaMemcpyToSymbolAsync(cW, Wf, GB, 0 * GB, cudaMemcpyDeviceToDevice);
    cudaMemcpyToSymbolAsync(cW, Wi, GB, 1 * GB, cudaMemcpyDeviceToDevice);
    cudaMemcpyToSymbolAsync(cW, Wu, GB, 2 * GB, cudaMemcpyDeviceToDevice);
    cudaMemcpyToSymbolAsync(cW, Wo, GB, 3 * GB, cudaMemcpyDeviceToDevice);

    qlstm_kernel<<<grid, THREADS>>>(x, hx, cx,
                                    bf, bi, bu, bo,
                                    tf, ti, tu, to, out, B);
}

// round 15
// speedup vs baseline: 11.7690x; 11.7690x over previous
#include <cuda_runtime.h>
#include <cstdint>

// _QuantumLSTMCell via warp-level mma.sync (HMMA bf16) GEMM, sm_103-safe PTX.
// angles = comb @ W^T + b ; z = cos(angle + th); E products; LSTM epilogue.
// D[128 x 16] = x[128 x 256] @ W^T as 3 bf16 GEMMs (hi*hi + hi*lo + lo*hi),
// fp32 accum. hx tail (k 256..259) exact fp32 in epilogue.
// Warp = 32 rows: 2 m-tiles x 2 n-tiles x 3 splits x 16 k16-chunks = 192 mma.

#define THREADS 128
#define WARPS 4
#define ROWS_WARP 32
#define ROWS_BLK 128
#define D_COLS 256
#define NJ 16
#define TILE_K 16
#define NTILES 16
#define PITCH 20                    // floats per staged row (conflict-free)
#define STAGE_F (ROWS_WARP * PITCH) // 640

__device__ __forceinline__ uint32_t cvt2(float hi, float lo) {
    uint32_t d;
    asm("cvt.rn.bf16x2.f32 %0, %1, %2;" : "=r"(d) : "f"(hi), "f"(lo));
    return d;
}
__device__ __forceinline__ float up_lo(uint32_t p) { return __uint_as_float(p << 16); }
__device__ __forceinline__ float up_hi(uint32_t p) { return __uint_as_float(p & 0xffff0000u); }

__device__ __forceinline__ void mma_bf16(float d[4], const uint32_t a[4],
                                         const uint32_t b[2]) {
    asm("mma.sync.aligned.m16n8k16.row.col.f32.bf16.bf16.f32 "
        "{%0,%1,%2,%3}, {%4,%5,%6,%7}, {%8,%9}, {%0,%1,%2,%3};"
        : "+f"(d[0]), "+f"(d[1]), "+f"(d[2]), "+f"(d[3])
        : "r"(a[0]), "r"(a[1]), "r"(a[2]), "r"(a[3]), "r"(b[0]), "r"(b[1]));
}

__device__ __forceinline__ void cp16(unsigned dst, const void* src) {
    asm volatile("cp.async.cg.shared.global [%0], [%1], 16;" :: "r"(dst), "l"(src));
}
__device__ __forceinline__ void cp_commit() { asm volatile("cp.async.commit_group;"); }
__device__ __forceinline__ void cp_wait1() { asm volatile("cp.async.wait_group 1;"); }
__device__ __forceinline__ void cp_wait0() { asm volatile("cp.async.wait_group 0;"); }

__device__ __forceinline__ float sigmoidf_(float x) {
    return 1.0f / (1.0f + __expf(-x));
}
__device__ __forceinline__ float tanhf_(float x) {
    return 1.0f - 2.0f / (__expf(2.0f * x) + 1.0f);
}

// issue one TILE_K=16 tile (32 rows x 64 B) for this warp (R12-proven map)
__device__ __forceinline__ void issue_tile(unsigned xs_s, const float* xw,
                                           int lane, int tile, int slot) {
#pragma unroll
    for (int i = 0; i < 4; i++) {
        int rl = i * 8 + (lane >> 2);
        int ch = lane & 3;
        cp16(xs_s + (unsigned)((slot * STAGE_F + rl * PITCH + ch * 4) * 4),
             xw + (size_t)rl * D_COLS + tile * TILE_K + ch * 4);
    }
    cp_commit();
}

// load + hi/lo split of one A fragment (m16 x k16) for this thread
__device__ __forceinline__ void load_a_frag(const float* xb, int r0, int g, int tg,
                                            uint32_t ahi[4], uint32_t alo[4]) {
    float2 f00 = *(const float2*)(xb + (r0 + g) * PITCH + 2 * tg);
    float2 f10 = *(const float2*)(xb + (r0 + g + 8) * PITCH + 2 * tg);
    float2 f01 = *(const float2*)(xb + (r0 + g) * PITCH + 2 * tg + 8);
    float2 f11 = *(const float2*)(xb + (r0 + g + 8) * PITCH + 2 * tg + 8);
    ahi[0] = cvt2(f00.y, f00.x);
    ahi[1] = cvt2(f10.y, f10.x);
    ahi[2] = cvt2(f01.y, f01.x);
    ahi[3] = cvt2(f11.y, f11.x);
    alo[0] = cvt2(f00.y - up_hi(ahi[0]), f00.x - up_lo(ahi[0]));
    alo[1] = cvt2(f10.y - up_hi(ahi[1]), f10.x - up_lo(ahi[1]));
    alo[2] = cvt2(f01.y - up_hi(ahi[2]), f01.x - up_lo(ahi[2]));
    alo[3] = cvt2(f11.y - up_hi(ahi[3]), f11.x - up_lo(ahi[3]));
}

__global__ void __launch_bounds__(THREADS, 5)
qlstm_mma_kernel(const float* __restrict__ x, const float* __restrict__ hx,
                 const float* __restrict__ cx,
                 const float* __restrict__ Wf, const float* __restrict__ Wi,
                 const float* __restrict__ Wu, const float* __restrict__ Wo,
                 const float* __restrict__ bf, const float* __restrict__ bi,
                 const float* __restrict__ bu, const float* __restrict__ bo,
                 const float* __restrict__ tf, const float* __restrict__ ti,
                 const float* __restrict__ tu, const float* __restrict__ to,
                 float* __restrict__ out, int B)
{
    // sB word index: ((chunk*2 + split)*16 + j)*8 + pos,
    // pos = (kp<4) ? 2*kp : 2*(kp-4)+1  -> thread LDS.64 at 2*tg gets kp=tg,tg+4
    __shared__ __align__(16) uint32_t sB[16 * 2 * 16 * 8];        // 16 KB
    __shared__ __align__(16) float xs[WARPS * 2 * STAGE_F];       // 20.5 KB
    __shared__ float hwt[NJ * 4];
    __shared__ float sphase[NJ];

    const int tid  = threadIdx.x;
    const int wid  = tid >> 5;
    const int lane = tid & 31;
    const int g    = lane >> 2;      // groupID
    const int tg   = lane & 3;       // threadID_in_group

    const int warpRow0 = blockIdx.x * ROWS_BLK + wid * ROWS_WARP;
    const float* xw = x + (size_t)warpRow0 * D_COLS;

    float* xs_w = xs + wid * (2 * STAGE_F);
    unsigned xs_s = (unsigned)__cvta_generic_to_shared(xs_w);

    // ---- prologue: tiles 0,1 ----
    issue_tile(xs_s, xw, lane, 0, 0);
    issue_tile(xs_s, xw, lane, 1, 1);

    // ---- stage split-B weights (once per block) ----
#pragma unroll 1
    for (int idx = tid; idx < NJ * 128; idx += THREADS) {   // j x 128 k-pairs
        int j = idx >> 7, kpg = idx & 127;
        int chunk = kpg >> 3, kpl = kpg & 7;
        const float* Wj = ((j < 4) ? Wf : (j < 8) ? Wi : (j < 12) ? Wu : Wo)
                          + (j & 3) * 260;
        float w0 = Wj[2 * kpg], w1 = Wj[2 * kpg + 1];
        uint32_t hi = cvt2(w1, w0);
        uint32_t lo = cvt2(w1 - up_hi(hi), w0 - up_lo(hi));
        int pos = (kpl < 4) ? 2 * kpl : 2 * (kpl - 4) + 1;
        sB[((chunk * 2 + 0) * 16 + j) * 8 + pos] = hi;
        sB[((chunk * 2 + 1) * 16 + j) * 8 + pos] = lo;
    }
    if (tid < 64) {     // exact fp32 weights for hx tail: hwt[j*4 + k]
        int j = tid >> 2, k = tid & 3;
        const float* Wj = ((j < 4) ? Wf : (j < 8) ? Wi : (j < 12) ? Wu : Wo)
                          + (j & 3) * 260;
        hwt[tid] = Wj[256 + k];
    }
    if (tid < NJ) {
        int j = tid, gate = j >> 2, wire = j & 3;
        const float* bb = (gate == 0) ? bf : (gate == 1) ? bi
                        : (gate == 2) ? bu : bo;
        const float* tt = (gate == 0) ? tf : (gate == 1) ? ti
                        : (gate == 2) ? tu : to;
        sphase[j] = bb[wire] + tt[wire];
    }
    __syncthreads();    // the ONLY block barrier

    float acc[2][2][4];
#pragma unroll
    for (int mt = 0; mt < 2; mt++)
#pragma unroll
        for (int nt = 0; nt < 2; nt++)
#pragma unroll
            for (int i = 0; i < 4; i++) acc[mt][nt][i] = 0.0f;

    // ---- warp-private pipelined main loop ----
#pragma unroll 1
    for (int t = 0; t < NTILES; t++) {
        if (t == NTILES - 1) cp_wait0(); else cp_wait1();
        __syncwarp();

        const float* xb = xs_w + (t & 1) * STAGE_F;

        uint32_t ahi[2][4], alo[2][4];
        load_a_frag(xb, 0,  g, tg, ahi[0], alo[0]);
        load_a_frag(xb, 16, g, tg, ahi[1], alo[1]);

        uint32_t bhi[2][2], blo[2][2];
#pragma unroll
        for (int nt = 0; nt < 2; nt++) {
            uint2 h = *(const uint2*)&sB[((t * 2 + 0) * 16 + nt * 8 + g) * 8 + 2 * tg];
            uint2 l = *(const uint2*)&sB[((t * 2 + 1) * 16 + nt * 8 + g) * 8 + 2 * tg];
            bhi[nt][0] = h.x; bhi[nt][1] = h.y;
            blo[nt][0] = l.x; blo[nt][1] = l.y;
        }

#pragma unroll
        for (int mt = 0; mt < 2; mt++)
#pragma unroll
            for (int nt = 0; nt < 2; nt++) {
                mma_bf16(acc[mt][nt], ahi[mt], bhi[nt]);   // hi*hi
                mma_bf16(acc[mt][nt], ahi[mt], blo[nt]);   // hi*lo
                mma_bf16(acc[mt][nt], alo[mt], bhi[nt]);   // lo*hi
            }
        __syncwarp();

        if (t + 2 < NTILES)
            issue_tile(xs_s, xw, lane, t + 2, t & 1);
    }

    // ---- exchange D through warp-private smem: eb[row_local][j], pitch 20 ----
    float* eb = xs_w;   // 32*20 floats = 2560 <= 5120
#pragma unroll
    for (int mt = 0; mt < 2; mt++)
#pragma unroll
        for (int nt = 0; nt < 2; nt++) {
            int r = mt * 16 + g, j = nt * 8 + 2 * tg;
            *(float2*)(eb + r * PITCH + j)       = make_float2(acc[mt][nt][0], acc[mt][nt][1]);
            *(float2*)(eb + (r + 8) * PITCH + j) = make_float2(acc[mt][nt][2], acc[mt][nt][3]);
        }
    __syncwarp();

    // ---- epilogue: thread owns row = lane ----
    const int row = warpRow0 + lane;
    float4 hv  = ((const float4*)hx)[row];
    float4 cxv = ((const float4*)cx)[row];
    const float4* hw4 = (const float4*)hwt;

    float z[NJ];
#pragma unroll
    for (int j = 0; j < NJ; j++) {
        float4 w = hw4[j];
        float ang = eb[lane * PITCH + j] + sphase[j]
                  + hv.x * w.x + hv.y * w.y + hv.z * w.z + hv.w * w.w;
        z[j] = __cosf(ang);
    }
    float e[NJ];
#pragma unroll
    for (int gg = 0; gg < 4; gg++) {
        float z0 = z[gg*4+0], z1 = z[gg*4+1], z2 = z[gg*4+2], z3 = z[gg*4+3];
        float p01 = z0 * z1;
        e[gg*4+0] = z1 * z2 * z3;
        e[gg*4+1] = p01;
        e[gg*4+2] = p01 * z2;
        e[gg*4+3] = p01 * z2 * z3;
    }
    float cxa[4] = {cxv.x, cxv.y, cxv.z, cxv.w};
    float hn[4], cn[4];
#pragma unroll
    for (int w = 0; w < 4; w++) {
        float fv = sigmoidf_(e[0*4+w]);
        float iv = sigmoidf_(e[1*4+w]);
        float gv = tanhf_(e[2*4+w]);
        float ov = sigmoidf_(e[3*4+w]);
        float c = fv * cxa[w] + iv * gv;
        cn[w] = c;
        hn[w] = ov * tanhf_(c);
    }
    ((float4*)out)[row] = make_float4(hn[0], hn[1], hn[2], hn[3]);
    ((float4*)(out + (size_t)B * 4))[row] = make_float4(cn[0], cn[1], cn[2], cn[3]);
}

extern "C" void kernel_launch(void* const* d_in, const int* in_sizes, int n_in,
                              void* d_out, int out_size) {
    const float* x  = (const float*)d_in[0];
    const float* hx = (const float*)d_in[1];
    const float* cx = (const float*)d_in[2];
    const float* Wf = (const float*)d_in[3];
    const float* bf = (const float*)d_in[4];
    const float* Wi = (const float*)d_in[5];
    const float* bi = (const float*)d_in[6];
    const float* Wu = (const float*)d_in[7];
    const float* bu = (const float*)d_in[8];
    const float* Wo = (const float*)d_in[9];
    const float* bo = (const float*)d_in[10];
    const float* tf = (const float*)d_in[11];
    const float* ti = (const float*)d_in[12];
    const float* tu = (const float*)d_in[13];
    const float* to = (const float*)d_in[14];
    float* out = (float*)d_out;

    int B = in_sizes[0] / D_COLS;                 // 131072
    int grid = (B + ROWS_BLK - 1) / ROWS_BLK;     // 1024

    qlstm_mma_kernel<<<grid, THREADS>>>(x, hx, cx, Wf, Wi, Wu, Wo,
                                        bf, bi, bu, bo,
                                        tf, ti, tu, to, out, B);
}